// round 10
// baseline (speedup 1.0000x reference)
#include <cuda_runtime.h>
#include <cuda_bf16.h>
#include <stdint.h>
#include <math.h>

#define D    4096
#define RK   1024
#define NTOT (1u << 24)     // 4^12 probability entries
#define PITB 80             // smem row pitch in BYTES (40 bf16) — conflict-free
#define TPIT 132            // epilogue transpose pitch (floats)

// ---------------------------------------------------------------------------
// Scratch (__device__ globals per allocation rules).
// ---------------------------------------------------------------------------
__device__ float gA_re[NTOT];
__device__ float gA_im[NTOT];
__device__ float gB_re[NTOT];
__device__ float gB_im[NTOT];
__device__ __nv_bfloat16 gHr[(size_t)D * RK];   // hi(Ur)
__device__ __nv_bfloat16 gLr[(size_t)D * RK];   // lo(Ur)
__device__ __nv_bfloat16 gHi[(size_t)D * RK];   // hi(Ui)
__device__ __nv_bfloat16 gLi[(size_t)D * RK];   // lo(Ui)
__device__ float g_inv_trace;

// ---------------------------------------------------------------------------
static __device__ __forceinline__ void mma16(float c[4], const uint32_t a[4],
                                             uint32_t b0, uint32_t b1) {
    asm volatile(
        "mma.sync.aligned.m16n8k16.row.col.f32.bf16.bf16.f32 "
        "{%0,%1,%2,%3}, {%4,%5,%6,%7}, {%8,%9}, {%0,%1,%2,%3};\n"
        : "+f"(c[0]), "+f"(c[1]), "+f"(c[2]), "+f"(c[3])
        : "r"(a[0]), "r"(a[1]), "r"(a[2]), "r"(a[3]), "r"(b0), "r"(b1));
}
static __device__ __forceinline__ void ldsm4(uint32_t r[4], uint32_t addr) {
    asm volatile("ldmatrix.sync.aligned.m8n8.x4.shared.b16 {%0,%1,%2,%3}, [%4];"
                 : "=r"(r[0]), "=r"(r[1]), "=r"(r[2]), "=r"(r[3]) : "r"(addr));
}

// ---------------------------------------------------------------------------
// Pack: hi = bf16(x), lo = bf16(x - hi) for both planes of U.
// ---------------------------------------------------------------------------
__global__ void __launch_bounds__(256) pack_split(const float* __restrict__ Ur,
                                                  const float* __restrict__ Ui)
{
    unsigned e = blockIdx.x * 256u + threadIdx.x;   // 0 .. 4M-1
    float x = Ur[e];
    __nv_bfloat16 h = __float2bfloat16_rn(x);
    gHr[e] = h;
    gLr[e] = __float2bfloat16_rn(x - __bfloat162float(h));
    float y = Ui[e];
    __nv_bfloat16 h2 = __float2bfloat16_rn(y);
    gHi[e] = h2;
    gLi[e] = __float2bfloat16_rn(y - __bfloat162float(h2));
}

// ---------------------------------------------------------------------------
// rho = U U^H via bf16x3 mma.sync (m16n8k16). Tile 128x128, triangular grid
// (528 CTAs, bi>=bj). K-chunk 32, double-buffered cp.async; 8 smem planes per
// stage: {Ar,Ai,Br,Bi} x {hi,lo}, rows pitched at 80B.  (R8 mainloop, proven;
// this round: fragment loads via ldmatrix.x4 — 24 LDSM vs 96 LDS per k16.)
// re = ArBr^T + AiBi^T ; im = AiBr^T - ArBi^T (minus via sign-flipped Ar).
// Split products kept: hh + hl + lh (lo*lo dropped).
// Epilogue: main tile via float2; mirror tile via smem transpose (coalesced).
// ---------------------------------------------------------------------------
__global__ void __launch_bounds__(256, 1) gemm_mma()
{
    extern __shared__ char sm[];    // 2 stages * 8 planes * 128*PITB bytes
    const uint32_t smb = (uint32_t)__cvta_generic_to_shared(sm);

    const int tid  = threadIdx.x;
    const int lane = tid & 31;
    const int wid  = tid >> 5;
    const int gid  = lane >> 2;     // 0..7
    const int tig  = lane & 3;      // 0..3
    const int wm   = wid >> 2;      // 0..1
    const int wn   = wid & 3;       // 0..3
    const int lrow = lane & 15;     // ldmatrix row within 16-row group
    const int lkof = (lane >> 4) * 16;  // ldmatrix 16B half selector

    // triangular tile index
    int l = blockIdx.x;
    int bi = (int)((sqrtf(8.0f * (float)l + 1.0f) - 1.0f) * 0.5f);
    while ((bi + 1) * (bi + 2) / 2 <= l) bi++;
    while (bi * (bi + 1) / 2 > l) bi--;
    int bj = l - bi * (bi + 1) / 2;
    const int row0 = bi * 128, col0 = bj * 128;

    const int PLNB = 128 * PITB;    // 10240 B per plane
    const int BUFB = 8 * PLNB;      // 81920 B per stage

    // plane order: 0 ArH, 1 ArL, 2 AiH, 3 AiL, 4 BrH, 5 BrL, 6 BiH, 7 BiL
    auto load_chunk = [&](int buf, int k0) {
        char* base = sm + buf * BUFB;
#pragma unroll
        for (int u = 0; u < 16; u++) {
            int i = tid + u * 256;          // 0..4095 16B slots
            int plane = i >> 9;             // 0..7
            int rem = i & 511;
            int r = rem >> 2;               // 0..127
            int q = rem & 3;                // 16B slot within 64B row-chunk
            const __nv_bfloat16* arr =
                (plane == 0 || plane == 4) ? gHr :
                (plane == 1 || plane == 5) ? gLr :
                (plane == 2 || plane == 6) ? gHi : gLi;
            int baser = (plane < 4) ? row0 : col0;
            const __nv_bfloat16* src =
                arr + (size_t)(baser + r) * RK + k0 + q * 8;
            uint32_t dst = (uint32_t)__cvta_generic_to_shared(
                base + plane * PLNB + r * PITB + q * 16);
            asm volatile("cp.async.cg.shared.global [%0], [%1], 16;"
                         :: "r"(dst), "l"(src));
        }
    };

    float accre[4][4][4], accim[4][4][4];
#pragma unroll
    for (int a = 0; a < 4; a++)
#pragma unroll
        for (int b = 0; b < 4; b++)
#pragma unroll
            for (int q = 0; q < 4; q++) { accre[a][b][q] = 0.f; accim[a][b][q] = 0.f; }

    load_chunk(0, 0);
    asm volatile("cp.async.commit_group;");

    // B frag selector over 8-reg arrays (two ldsm4): nf0:(0,2) nf1:(1,3) nf2:(4,6) nf3:(5,7)
#define BSEL(P, nf) P[((nf) & 1) + ((nf) >> 1) * 4], P[((nf) & 1) + ((nf) >> 1) * 4 + 2]

#pragma unroll 1
    for (int c = 0; c < 32; c++) {
        if (c + 1 < 32) load_chunk((c + 1) & 1, (c + 1) * 32);
        asm volatile("cp.async.commit_group;");
        asm volatile("cp.async.wait_group 1;");
        __syncthreads();

        const uint32_t sbb = smb + (c & 1) * BUFB;

#pragma unroll
        for (int kk = 0; kk < 2; kk++) {      // two k16 halves of the 32-chunk
            const uint32_t ko = kk * 32 + lkof;

            // ---- B fragments via ldmatrix: 4 planes x 2 ldsm4 ----
            uint32_t BrH[8], BrL[8], BiH[8], BiL[8];
            {
                uint32_t b0 = sbb + 4 * PLNB + (wn * 32 + lrow) * PITB + ko;
                uint32_t b1 = sbb + 4 * PLNB + (wn * 32 + 16 + lrow) * PITB + ko;
                ldsm4(BrH,     b0);            ldsm4(BrH + 4, b1);
                ldsm4(BrL,     b0 + PLNB);     ldsm4(BrL + 4, b1 + PLNB);
                ldsm4(BiH,     b0 + 2 * PLNB); ldsm4(BiH + 4, b1 + 2 * PLNB);
                ldsm4(BiL,     b0 + 3 * PLNB); ldsm4(BiL + 4, b1 + 3 * PLNB);
            }

            uint32_t AH[4][4], AL[4][4];
            // ---- plane Ar (hi/lo) via ldmatrix ----
#pragma unroll
            for (int mf = 0; mf < 4; mf++) {
                uint32_t aa = sbb + (wm * 64 + mf * 16 + lrow) * PITB + ko;
                ldsm4(AH[mf], aa);
                ldsm4(AL[mf], aa + PLNB);
            }
            // re += Ar*Br (hh, hl, lh)
#pragma unroll
            for (int mf = 0; mf < 4; mf++)
#pragma unroll
                for (int nf = 0; nf < 4; nf++) {
                    mma16(accre[mf][nf], AH[mf], BSEL(BrH, nf));
                    mma16(accre[mf][nf], AH[mf], BSEL(BrL, nf));
                    mma16(accre[mf][nf], AL[mf], BSEL(BrH, nf));
                }
            // im += (-Ar)*Bi  (exact sign flip of both bf16 halves)
#pragma unroll
            for (int mf = 0; mf < 4; mf++)
#pragma unroll
                for (int q = 0; q < 4; q++) {
                    AH[mf][q] ^= 0x80008000u;
                    AL[mf][q] ^= 0x80008000u;
                }
#pragma unroll
            for (int mf = 0; mf < 4; mf++)
#pragma unroll
                for (int nf = 0; nf < 4; nf++) {
                    mma16(accim[mf][nf], AH[mf], BSEL(BiH, nf));
                    mma16(accim[mf][nf], AH[mf], BSEL(BiL, nf));
                    mma16(accim[mf][nf], AL[mf], BSEL(BiH, nf));
                }
            // ---- plane Ai (hi/lo) via ldmatrix ----
#pragma unroll
            for (int mf = 0; mf < 4; mf++) {
                uint32_t aa = sbb + 2 * PLNB + (wm * 64 + mf * 16 + lrow) * PITB + ko;
                ldsm4(AH[mf], aa);
                ldsm4(AL[mf], aa + PLNB);
            }
            // re += Ai*Bi
#pragma unroll
            for (int mf = 0; mf < 4; mf++)
#pragma unroll
                for (int nf = 0; nf < 4; nf++) {
                    mma16(accre[mf][nf], AH[mf], BSEL(BiH, nf));
                    mma16(accre[mf][nf], AH[mf], BSEL(BiL, nf));
                    mma16(accre[mf][nf], AL[mf], BSEL(BiH, nf));
                }
            // im += Ai*Br
#pragma unroll
            for (int mf = 0; mf < 4; mf++)
#pragma unroll
                for (int nf = 0; nf < 4; nf++) {
                    mma16(accim[mf][nf], AH[mf], BSEL(BrH, nf));
                    mma16(accim[mf][nf], AH[mf], BSEL(BrL, nf));
                    mma16(accim[mf][nf], AL[mf], BSEL(BrH, nf));
                }
        }
        __syncthreads();
    }
#undef BSEL

    // drain cp.async before reusing smem for the transpose
    asm volatile("cp.async.wait_group 0;");
    __syncthreads();

    // ---- main tile writes (row-major, float2 per store) ----
#pragma unroll
    for (int mf = 0; mf < 4; mf++)
#pragma unroll
        for (int nf = 0; nf < 4; nf++) {
            unsigned r  = row0 + wm * 64 + mf * 16 + gid;
            unsigned cc = col0 + wn * 32 + nf * 8 + 2 * tig;
            const float* cr = accre[mf][nf];
            const float* ci = accim[mf][nf];
            *(float2*)&gA_re[(size_t)r * D + cc]       = make_float2(cr[0], cr[1]);
            *(float2*)&gA_re[(size_t)(r + 8) * D + cc] = make_float2(cr[2], cr[3]);
            *(float2*)&gA_im[(size_t)r * D + cc]       = make_float2(ci[0], ci[1]);
            *(float2*)&gA_im[(size_t)(r + 8) * D + cc] = make_float2(ci[2], ci[3]);
        }

    // ---- mirror writes via smem transpose (coalesced 512B rows) ----
    if (bi != bj) {
        float* smf = (float*)sm;    // 128 x TPIT floats = 67584 B (< smem)
#pragma unroll 1
        for (int pl = 0; pl < 2; pl++) {
            float sgn = pl ? -1.f : 1.f;
#pragma unroll
            for (int mf = 0; mf < 4; mf++)
#pragma unroll
                for (int nf = 0; nf < 4; nf++) {
                    int rL  = wm * 64 + mf * 16 + gid;
                    int ccL = wn * 32 + nf * 8 + 2 * tig;
                    const float* v = pl ? accim[mf][nf] : accre[mf][nf];
                    smf[(ccL)     * TPIT + rL]     = sgn * v[0];
                    smf[(ccL + 1) * TPIT + rL]     = sgn * v[1];
                    smf[(ccL)     * TPIT + rL + 8] = sgn * v[2];
                    smf[(ccL + 1) * TPIT + rL + 8] = sgn * v[3];
                }
            __syncthreads();
            float* gout = pl ? gA_im : gA_re;
#pragma unroll
            for (int r8 = 0; r8 < 16; r8++) {
                int mr = wid * 16 + r8;
                float4 v = *(float4*)&smf[mr * TPIT + lane * 4];
                *(float4*)&gout[(size_t)(col0 + mr) * D + row0 + lane * 4] = v;
            }
            __syncthreads();
        }
    }
}

// ---------------------------------------------------------------------------
// trace: sum of re diagonal of rho -> 1/trace
// ---------------------------------------------------------------------------
__global__ void trace_kernel()
{
    __shared__ float red[256];
    float s = 0.f;
    for (int i = threadIdx.x; i < D; i += 256)
        s += gA_re[(size_t)i * D + i];
    red[threadIdx.x] = s;
    __syncthreads();
    for (int w = 128; w; w >>= 1) {
        if (threadIdx.x < w) red[threadIdx.x] += red[threadIdx.x + w];
        __syncthreads();
    }
    if (threadIdx.x == 0) g_inv_trace = 1.0f / red[0];
}

// ---------------------------------------------------------------------------
// Fused 2-qubit partial-trace sweep, factored into two 4-term complex stages.
// dir=0: A->B, dir=1: B->A. wim=0 skips imag store (last sweep).
// ---------------------------------------------------------------------------
__global__ void __launch_bounds__(256) qmt_sweep(int dir,
                                                 const float* __restrict__ Mr,
                                                 const float* __restrict__ Mi,
                                                 int lc, int wim)
{
    const float* __restrict__ in_re = dir ? gB_re : gA_re;
    const float* __restrict__ in_im = dir ? gB_im : gA_im;
    float* __restrict__ o_re = dir ? gA_re : gB_re;
    float* __restrict__ o_im = dir ? gA_im : gB_im;

    __shared__ float sr[16], si[16];   // M[s,i,j] at s*4+i*2+j
    int tid = threadIdx.x;
    if (tid < 16) { sr[tid] = Mr[tid]; si[tid] = Mi[tid]; }
    __syncthreads();

    unsigned gid = blockIdx.x * 256u + (unsigned)tid;   // 0 .. 2^20-1
    unsigned cp = 1u << lc;
    unsigned t = gid & (cp - 1u);
    unsigned a = (gid >> lc) & (cp - 1u);
    unsigned k = gid >> (2 * lc);
    unsigned base_in = k << (2 * lc + 4);

    float xr[16], xi[16];
#pragma unroll
    for (int J = 0; J < 4; J++)
#pragma unroll
        for (int I = 0; I < 4; I++) {
            unsigned off = base_in
                         + ((((unsigned)J << lc) + a) << (lc + 2))
                         + ((unsigned)I << lc) + t;
            xr[J * 4 + I] = in_re[off];
            xi[J * 4 + I] = in_im[off];
        }

    // stage 1: contract (j1,i1): y[s1][(j2,i2)]
    float yr[16], yi[16];
#pragma unroll
    for (int s1 = 0; s1 < 4; s1++)
#pragma unroll
        for (int j2 = 0; j2 < 2; j2++)
#pragma unroll
            for (int i2 = 0; i2 < 2; i2++) {
                float ar = 0.f, ai = 0.f;
#pragma unroll
                for (int j1 = 0; j1 < 2; j1++)
#pragma unroll
                    for (int i1 = 0; i1 < 2; i1++) {
                        float mr = sr[s1 * 4 + i1 * 2 + j1];
                        float mi = si[s1 * 4 + i1 * 2 + j1];
                        float vr = xr[(j1 * 2 + j2) * 4 + i1 * 2 + i2];
                        float vi = xi[(j1 * 2 + j2) * 4 + i1 * 2 + i2];
                        ar = fmaf(mr, vr, ar); ar = fmaf(-mi, vi, ar);
                        ai = fmaf(mr, vi, ai); ai = fmaf(mi, vr, ai);
                    }
                yr[s1 * 4 + j2 * 2 + i2] = ar;
                yi[s1 * 4 + j2 * 2 + i2] = ai;
            }

    // stage 2: contract (j2,i2)
#pragma unroll
    for (int s1 = 0; s1 < 4; s1++)
#pragma unroll
        for (int s2 = 0; s2 < 4; s2++) {
            float aR = 0.f, aI = 0.f;
#pragma unroll
            for (int j2 = 0; j2 < 2; j2++)
#pragma unroll
                for (int i2 = 0; i2 < 2; i2++) {
                    float mr = sr[s2 * 4 + i2 * 2 + j2];
                    float mi = si[s2 * 4 + i2 * 2 + j2];
                    float vr = yr[s1 * 4 + j2 * 2 + i2];
                    float vi = yi[s1 * 4 + j2 * 2 + i2];
                    aR = fmaf(mr, vr, aR); aR = fmaf(-mi, vi, aR);
                    aI = fmaf(mr, vi, aI); aI = fmaf(mi, vr, aI);
                }
            unsigned off = (((k << 4) + (unsigned)(s1 * 4 + s2)) << (2 * lc))
                         + (a << lc) + t;
            o_re[off] = aR;
            if (wim) o_im[off] = aI;
        }
}

// ---------------------------------------------------------------------------
// Gather: out[i] = P_all[idx[i]] / trace (real plane only; int32 indices).
// ---------------------------------------------------------------------------
__global__ void gather_kernel(const int* __restrict__ idx,
                              float* __restrict__ out, int n)
{
    int i = blockIdx.x * 256 + threadIdx.x;
    if (i < n) out[i] = gA_re[(unsigned)idx[i] & (NTOT - 1u)] * g_inv_trace;
}

// ---------------------------------------------------------------------------
extern "C" void kernel_launch(void* const* d_in, const int* in_sizes, int n_in,
                              void* d_out, int out_size)
{
    const float* params = (const float*)d_in[0];      // (2, 4096, 1024)
    const float* Mr = (const float*)d_in[1];          // (4,2,2)
    const float* Mi = (const float*)d_in[2];          // (4,2,2)
    const int* idx = (const int*)d_in[3];             // (1e6,) int32
    float* out = (float*)d_out;

    const float* Ur = params;
    const float* Ui = params + (size_t)D * RK;

    pack_split<<<16384, 256>>>(Ur, Ui);

    const int smem_bytes = 2 * 8 * 128 * PITB;        // 163840
    cudaFuncSetAttribute(gemm_mma,
                         cudaFuncAttributeMaxDynamicSharedMemorySize, smem_bytes);
    gemm_mma<<<528, 256, smem_bytes>>>();

    trace_kernel<<<1, 256>>>();

    int dir = 0;
    for (int n = 1; n <= 6; n++) {
        qmt_sweep<<<4096, 256>>>(dir, Mr, Mi, 12 - 2 * n, n < 6 ? 1 : 0);
        dir ^= 1;
    }
    // final result (real plane) in gA_re

    int nq = in_sizes[3];
    gather_kernel<<<(nq + 255) / 256, 256>>>(idx, out, nq);
}

// round 11
// speedup vs baseline: 1.1330x; 1.1330x over previous
#include <cuda_runtime.h>
#include <cuda_bf16.h>
#include <stdint.h>
#include <math.h>

#define D    4096
#define RK   1024
#define NTOT (1u << 24)     // 4^12 probability entries
#define PITB 80             // smem row pitch in BYTES (40 bf16) — conflict-free
#define TPIT 132            // epilogue transpose pitch (floats)

// ---------------------------------------------------------------------------
// Scratch (__device__ globals per allocation rules).
// ---------------------------------------------------------------------------
__device__ float gA_re[NTOT];
__device__ float gA_im[NTOT];
__device__ float gB_re[NTOT];
__device__ float gB_im[NTOT];
__device__ __nv_bfloat16 gHr[(size_t)D * RK];   // hi(Ur)
__device__ __nv_bfloat16 gLr[(size_t)D * RK];   // lo(Ur)
__device__ __nv_bfloat16 gHi[(size_t)D * RK];   // hi(Ui)
__device__ __nv_bfloat16 gLi[(size_t)D * RK];   // lo(Ui)
__device__ float g_inv_trace;

// ---------------------------------------------------------------------------
static __device__ __forceinline__ void mma16(float c[4], const uint32_t a[4],
                                             const uint32_t b[2]) {
    asm volatile(
        "mma.sync.aligned.m16n8k16.row.col.f32.bf16.bf16.f32 "
        "{%0,%1,%2,%3}, {%4,%5,%6,%7}, {%8,%9}, {%0,%1,%2,%3};\n"
        : "+f"(c[0]), "+f"(c[1]), "+f"(c[2]), "+f"(c[3])
        : "r"(a[0]), "r"(a[1]), "r"(a[2]), "r"(a[3]), "r"(b[0]), "r"(b[1]));
}
static __device__ __forceinline__ uint32_t lds32(const char* base, int off) {
    return *(const uint32_t*)(base + off);
}

// ---------------------------------------------------------------------------
// Pack: hi = bf16(x), lo = bf16(x - hi) for both planes of U.
// ---------------------------------------------------------------------------
__global__ void __launch_bounds__(256) pack_split(const float* __restrict__ Ur,
                                                  const float* __restrict__ Ui)
{
    unsigned e = blockIdx.x * 256u + threadIdx.x;   // 0 .. 4M-1
    float x = Ur[e];
    __nv_bfloat16 h = __float2bfloat16_rn(x);
    gHr[e] = h;
    gLr[e] = __float2bfloat16_rn(x - __bfloat162float(h));
    float y = Ui[e];
    __nv_bfloat16 h2 = __float2bfloat16_rn(y);
    gHi[e] = h2;
    gLi[e] = __float2bfloat16_rn(y - __bfloat162float(h2));
}

// ---------------------------------------------------------------------------
// rho = U U^H via bf16x3 mma.sync (m16n8k16). Tile 128x128, triangular grid
// (528 CTAs, bi>=bj). K-chunk 32, double-buffered cp.async; 8 smem planes per
// stage: {Ar,Ai,Br,Bi} x {hi,lo}, rows pitched at 80B.  (R8 base, proven.)
// THIS ROUND'S ONLY CHANGE: MMA order is term-outermost — all 16 independent
// hh MMAs, then 16 hl, then 16 lh — so dependent HMMAs on the same
// accumulator are 16 instructions apart (was 1). Same per-acc hh->hl->lh
// order => bit-identical arithmetic.
// re = ArBr^T + AiBi^T ; im = AiBr^T - ArBi^T (minus via sign-flipped Ar).
// Epilogue: main tile via float2; mirror tile via smem transpose (coalesced).
// ---------------------------------------------------------------------------
__global__ void __launch_bounds__(256, 1) gemm_mma()
{
    extern __shared__ char sm[];    // 2 stages * 8 planes * 128*PITB bytes

    const int tid  = threadIdx.x;
    const int lane = tid & 31;
    const int wid  = tid >> 5;
    const int gid  = lane >> 2;     // 0..7
    const int tig  = lane & 3;      // 0..3
    const int wm   = wid >> 2;      // 0..1
    const int wn   = wid & 3;       // 0..3

    // triangular tile index
    int l = blockIdx.x;
    int bi = (int)((sqrtf(8.0f * (float)l + 1.0f) - 1.0f) * 0.5f);
    while ((bi + 1) * (bi + 2) / 2 <= l) bi++;
    while (bi * (bi + 1) / 2 > l) bi--;
    int bj = l - bi * (bi + 1) / 2;
    const int row0 = bi * 128, col0 = bj * 128;

    const int PLNB = 128 * PITB;    // 10240 B per plane
    const int BUFB = 8 * PLNB;      // 81920 B per stage

    // plane order: 0 ArH, 1 ArL, 2 AiH, 3 AiL, 4 BrH, 5 BrL, 6 BiH, 7 BiL
    auto load_chunk = [&](int buf, int k0) {
        char* base = sm + buf * BUFB;
#pragma unroll
        for (int u = 0; u < 16; u++) {
            int i = tid + u * 256;          // 0..4095 16B slots
            int plane = i >> 9;             // 0..7
            int rem = i & 511;
            int r = rem >> 2;               // 0..127
            int q = rem & 3;                // 16B slot within 64B row-chunk
            const __nv_bfloat16* arr =
                (plane == 0 || plane == 4) ? gHr :
                (plane == 1 || plane == 5) ? gLr :
                (plane == 2 || plane == 6) ? gHi : gLi;
            int baser = (plane < 4) ? row0 : col0;
            const __nv_bfloat16* src =
                arr + (size_t)(baser + r) * RK + k0 + q * 8;
            uint32_t dst = (uint32_t)__cvta_generic_to_shared(
                base + plane * PLNB + r * PITB + q * 16);
            asm volatile("cp.async.cg.shared.global [%0], [%1], 16;"
                         :: "r"(dst), "l"(src));
        }
    };

    float accre[4][4][4], accim[4][4][4];
#pragma unroll
    for (int a = 0; a < 4; a++)
#pragma unroll
        for (int b = 0; b < 4; b++)
#pragma unroll
            for (int q = 0; q < 4; q++) { accre[a][b][q] = 0.f; accim[a][b][q] = 0.f; }

    load_chunk(0, 0);
    asm volatile("cp.async.commit_group;");

#pragma unroll 1
    for (int c = 0; c < 32; c++) {
        if (c + 1 < 32) load_chunk((c + 1) & 1, (c + 1) * 32);
        asm volatile("cp.async.commit_group;");
        asm volatile("cp.async.wait_group 1;");
        __syncthreads();

        const char* bb = sm + (c & 1) * BUFB;

#pragma unroll
        for (int kk = 0; kk < 2; kk++) {      // two k16 halves of the 32-chunk
            const int kbyte = kk * 32 + tig * 4;   // within-row byte offset

            // ---- B fragments: BrH, BrL, BiH, BiL (2 regs x 4 nf each) ----
            uint32_t BrH[4][2], BrL[4][2], BiH[4][2], BiL[4][2];
#pragma unroll
            for (int nf = 0; nf < 4; nf++) {
                int n = (wn * 32 + nf * 8 + gid) * PITB;
                BrH[nf][0] = lds32(bb + 4 * PLNB, n + kbyte);
                BrH[nf][1] = lds32(bb + 4 * PLNB, n + kbyte + 16);
                BrL[nf][0] = lds32(bb + 5 * PLNB, n + kbyte);
                BrL[nf][1] = lds32(bb + 5 * PLNB, n + kbyte + 16);
                BiH[nf][0] = lds32(bb + 6 * PLNB, n + kbyte);
                BiH[nf][1] = lds32(bb + 6 * PLNB, n + kbyte + 16);
                BiL[nf][0] = lds32(bb + 7 * PLNB, n + kbyte);
                BiL[nf][1] = lds32(bb + 7 * PLNB, n + kbyte + 16);
            }

            uint32_t AH[4][4], AL[4][4];
            // ---- plane Ar (hi/lo) ----
#pragma unroll
            for (int mf = 0; mf < 4; mf++) {
                int r = (wm * 64 + mf * 16 + gid) * PITB;
                AH[mf][0] = lds32(bb,        r + kbyte);
                AH[mf][1] = lds32(bb,        r + 8 * PITB + kbyte);
                AH[mf][2] = lds32(bb,        r + kbyte + 16);
                AH[mf][3] = lds32(bb,        r + 8 * PITB + kbyte + 16);
                AL[mf][0] = lds32(bb + PLNB, r + kbyte);
                AL[mf][1] = lds32(bb + PLNB, r + 8 * PITB + kbyte);
                AL[mf][2] = lds32(bb + PLNB, r + kbyte + 16);
                AL[mf][3] = lds32(bb + PLNB, r + 8 * PITB + kbyte + 16);
            }
            // re += Ar*Br : hh (16 indep), then hl, then lh
#pragma unroll
            for (int mf = 0; mf < 4; mf++)
#pragma unroll
                for (int nf = 0; nf < 4; nf++) mma16(accre[mf][nf], AH[mf], BrH[nf]);
#pragma unroll
            for (int mf = 0; mf < 4; mf++)
#pragma unroll
                for (int nf = 0; nf < 4; nf++) mma16(accre[mf][nf], AH[mf], BrL[nf]);
#pragma unroll
            for (int mf = 0; mf < 4; mf++)
#pragma unroll
                for (int nf = 0; nf < 4; nf++) mma16(accre[mf][nf], AL[mf], BrH[nf]);
            // im += (-Ar)*Bi  (exact sign flip of both bf16 halves)
#pragma unroll
            for (int mf = 0; mf < 4; mf++)
#pragma unroll
                for (int q = 0; q < 4; q++) {
                    AH[mf][q] ^= 0x80008000u;
                    AL[mf][q] ^= 0x80008000u;
                }
#pragma unroll
            for (int mf = 0; mf < 4; mf++)
#pragma unroll
                for (int nf = 0; nf < 4; nf++) mma16(accim[mf][nf], AH[mf], BiH[nf]);
#pragma unroll
            for (int mf = 0; mf < 4; mf++)
#pragma unroll
                for (int nf = 0; nf < 4; nf++) mma16(accim[mf][nf], AH[mf], BiL[nf]);
#pragma unroll
            for (int mf = 0; mf < 4; mf++)
#pragma unroll
                for (int nf = 0; nf < 4; nf++) mma16(accim[mf][nf], AL[mf], BiH[nf]);
            // ---- plane Ai (hi/lo) ----
#pragma unroll
            for (int mf = 0; mf < 4; mf++) {
                int r = (wm * 64 + mf * 16 + gid) * PITB;
                AH[mf][0] = lds32(bb + 2 * PLNB, r + kbyte);
                AH[mf][1] = lds32(bb + 2 * PLNB, r + 8 * PITB + kbyte);
                AH[mf][2] = lds32(bb + 2 * PLNB, r + kbyte + 16);
                AH[mf][3] = lds32(bb + 2 * PLNB, r + 8 * PITB + kbyte + 16);
                AL[mf][0] = lds32(bb + 3 * PLNB, r + kbyte);
                AL[mf][1] = lds32(bb + 3 * PLNB, r + 8 * PITB + kbyte);
                AL[mf][2] = lds32(bb + 3 * PLNB, r + kbyte + 16);
                AL[mf][3] = lds32(bb + 3 * PLNB, r + 8 * PITB + kbyte + 16);
            }
            // re += Ai*Bi
#pragma unroll
            for (int mf = 0; mf < 4; mf++)
#pragma unroll
                for (int nf = 0; nf < 4; nf++) mma16(accre[mf][nf], AH[mf], BiH[nf]);
#pragma unroll
            for (int mf = 0; mf < 4; mf++)
#pragma unroll
                for (int nf = 0; nf < 4; nf++) mma16(accre[mf][nf], AH[mf], BiL[nf]);
#pragma unroll
            for (int mf = 0; mf < 4; mf++)
#pragma unroll
                for (int nf = 0; nf < 4; nf++) mma16(accre[mf][nf], AL[mf], BiH[nf]);
            // im += Ai*Br
#pragma unroll
            for (int mf = 0; mf < 4; mf++)
#pragma unroll
                for (int nf = 0; nf < 4; nf++) mma16(accim[mf][nf], AH[mf], BrH[nf]);
#pragma unroll
            for (int mf = 0; mf < 4; mf++)
#pragma unroll
                for (int nf = 0; nf < 4; nf++) mma16(accim[mf][nf], AH[mf], BrL[nf]);
#pragma unroll
            for (int mf = 0; mf < 4; mf++)
#pragma unroll
                for (int nf = 0; nf < 4; nf++) mma16(accim[mf][nf], AL[mf], BrH[nf]);
        }
        __syncthreads();
    }

    // drain cp.async before reusing smem for the transpose
    asm volatile("cp.async.wait_group 0;");
    __syncthreads();

    // ---- main tile writes (row-major, float2 per store) ----
#pragma unroll
    for (int mf = 0; mf < 4; mf++)
#pragma unroll
        for (int nf = 0; nf < 4; nf++) {
            unsigned r  = row0 + wm * 64 + mf * 16 + gid;
            unsigned cc = col0 + wn * 32 + nf * 8 + 2 * tig;
            const float* cr = accre[mf][nf];
            const float* ci = accim[mf][nf];
            *(float2*)&gA_re[(size_t)r * D + cc]       = make_float2(cr[0], cr[1]);
            *(float2*)&gA_re[(size_t)(r + 8) * D + cc] = make_float2(cr[2], cr[3]);
            *(float2*)&gA_im[(size_t)r * D + cc]       = make_float2(ci[0], ci[1]);
            *(float2*)&gA_im[(size_t)(r + 8) * D + cc] = make_float2(ci[2], ci[3]);
        }

    // ---- mirror writes via smem transpose (coalesced 512B rows) ----
    if (bi != bj) {
        float* smf = (float*)sm;    // 128 x TPIT floats = 67584 B (< smem)
#pragma unroll 1
        for (int pl = 0; pl < 2; pl++) {
            float sgn = pl ? -1.f : 1.f;
#pragma unroll
            for (int mf = 0; mf < 4; mf++)
#pragma unroll
                for (int nf = 0; nf < 4; nf++) {
                    int rL  = wm * 64 + mf * 16 + gid;
                    int ccL = wn * 32 + nf * 8 + 2 * tig;
                    const float* v = pl ? accim[mf][nf] : accre[mf][nf];
                    smf[(ccL)     * TPIT + rL]     = sgn * v[0];
                    smf[(ccL + 1) * TPIT + rL]     = sgn * v[1];
                    smf[(ccL)     * TPIT + rL + 8] = sgn * v[2];
                    smf[(ccL + 1) * TPIT + rL + 8] = sgn * v[3];
                }
            __syncthreads();
            float* gout = pl ? gA_im : gA_re;
#pragma unroll
            for (int r8 = 0; r8 < 16; r8++) {
                int mr = wid * 16 + r8;
                float4 v = *(float4*)&smf[mr * TPIT + lane * 4];
                *(float4*)&gout[(size_t)(col0 + mr) * D + row0 + lane * 4] = v;
            }
            __syncthreads();
        }
    }
}

// ---------------------------------------------------------------------------
// trace: sum of re diagonal of rho -> 1/trace
// ---------------------------------------------------------------------------
__global__ void trace_kernel()
{
    __shared__ float red[256];
    float s = 0.f;
    for (int i = threadIdx.x; i < D; i += 256)
        s += gA_re[(size_t)i * D + i];
    red[threadIdx.x] = s;
    __syncthreads();
    for (int w = 128; w; w >>= 1) {
        if (threadIdx.x < w) red[threadIdx.x] += red[threadIdx.x + w];
        __syncthreads();
    }
    if (threadIdx.x == 0) g_inv_trace = 1.0f / red[0];
}

// ---------------------------------------------------------------------------
// Fused 2-qubit partial-trace sweep, factored into two 4-term complex stages.
// dir=0: A->B, dir=1: B->A. wim=0 skips imag store (last sweep).
// ---------------------------------------------------------------------------
__global__ void __launch_bounds__(256) qmt_sweep(int dir,
                                                 const float* __restrict__ Mr,
                                                 const float* __restrict__ Mi,
                                                 int lc, int wim)
{
    const float* __restrict__ in_re = dir ? gB_re : gA_re;
    const float* __restrict__ in_im = dir ? gB_im : gA_im;
    float* __restrict__ o_re = dir ? gA_re : gB_re;
    float* __restrict__ o_im = dir ? gA_im : gB_im;

    __shared__ float sr[16], si[16];   // M[s,i,j] at s*4+i*2+j
    int tid = threadIdx.x;
    if (tid < 16) { sr[tid] = Mr[tid]; si[tid] = Mi[tid]; }
    __syncthreads();

    unsigned gid = blockIdx.x * 256u + (unsigned)tid;   // 0 .. 2^20-1
    unsigned cp = 1u << lc;
    unsigned t = gid & (cp - 1u);
    unsigned a = (gid >> lc) & (cp - 1u);
    unsigned k = gid >> (2 * lc);
    unsigned base_in = k << (2 * lc + 4);

    float xr[16], xi[16];
#pragma unroll
    for (int J = 0; J < 4; J++)
#pragma unroll
        for (int I = 0; I < 4; I++) {
            unsigned off = base_in
                         + ((((unsigned)J << lc) + a) << (lc + 2))
                         + ((unsigned)I << lc) + t;
            xr[J * 4 + I] = in_re[off];
            xi[J * 4 + I] = in_im[off];
        }

    // stage 1: contract (j1,i1): y[s1][(j2,i2)]
    float yr[16], yi[16];
#pragma unroll
    for (int s1 = 0; s1 < 4; s1++)
#pragma unroll
        for (int j2 = 0; j2 < 2; j2++)
#pragma unroll
            for (int i2 = 0; i2 < 2; i2++) {
                float ar = 0.f, ai = 0.f;
#pragma unroll
                for (int j1 = 0; j1 < 2; j1++)
#pragma unroll
                    for (int i1 = 0; i1 < 2; i1++) {
                        float mr = sr[s1 * 4 + i1 * 2 + j1];
                        float mi = si[s1 * 4 + i1 * 2 + j1];
                        float vr = xr[(j1 * 2 + j2) * 4 + i1 * 2 + i2];
                        float vi = xi[(j1 * 2 + j2) * 4 + i1 * 2 + i2];
                        ar = fmaf(mr, vr, ar); ar = fmaf(-mi, vi, ar);
                        ai = fmaf(mr, vi, ai); ai = fmaf(mi, vr, ai);
                    }
                yr[s1 * 4 + j2 * 2 + i2] = ar;
                yi[s1 * 4 + j2 * 2 + i2] = ai;
            }

    // stage 2: contract (j2,i2)
#pragma unroll
    for (int s1 = 0; s1 < 4; s1++)
#pragma unroll
        for (int s2 = 0; s2 < 4; s2++) {
            float aR = 0.f, aI = 0.f;
#pragma unroll
            for (int j2 = 0; j2 < 2; j2++)
#pragma unroll
                for (int i2 = 0; i2 < 2; i2++) {
                    float mr = sr[s2 * 4 + i2 * 2 + j2];
                    float mi = si[s2 * 4 + i2 * 2 + j2];
                    float vr = yr[s1 * 4 + j2 * 2 + i2];
                    float vi = yi[s1 * 4 + j2 * 2 + i2];
                    aR = fmaf(mr, vr, aR); aR = fmaf(-mi, vi, aR);
                    aI = fmaf(mr, vi, aI); aI = fmaf(mi, vr, aI);
                }
            unsigned off = (((k << 4) + (unsigned)(s1 * 4 + s2)) << (2 * lc))
                         + (a << lc) + t;
            o_re[off] = aR;
            if (wim) o_im[off] = aI;
        }
}

// ---------------------------------------------------------------------------
// Gather: out[i] = P_all[idx[i]] / trace (real plane only; int32 indices).
// ---------------------------------------------------------------------------
__global__ void gather_kernel(const int* __restrict__ idx,
                              float* __restrict__ out, int n)
{
    int i = blockIdx.x * 256 + threadIdx.x;
    if (i < n) out[i] = gA_re[(unsigned)idx[i] & (NTOT - 1u)] * g_inv_trace;
}

// ---------------------------------------------------------------------------
extern "C" void kernel_launch(void* const* d_in, const int* in_sizes, int n_in,
                              void* d_out, int out_size)
{
    const float* params = (const float*)d_in[0];      // (2, 4096, 1024)
    const float* Mr = (const float*)d_in[1];          // (4,2,2)
    const float* Mi = (const float*)d_in[2];          // (4,2,2)
    const int* idx = (const int*)d_in[3];             // (1e6,) int32
    float* out = (float*)d_out;

    const float* Ur = params;
    const float* Ui = params + (size_t)D * RK;

    pack_split<<<16384, 256>>>(Ur, Ui);

    const int smem_bytes = 2 * 8 * 128 * PITB;        // 163840
    cudaFuncSetAttribute(gemm_mma,
                         cudaFuncAttributeMaxDynamicSharedMemorySize, smem_bytes);
    gemm_mma<<<528, 256, smem_bytes>>>();

    trace_kernel<<<1, 256>>>();

    int dir = 0;
    for (int n = 1; n <= 6; n++) {
        qmt_sweep<<<4096, 256>>>(dir, Mr, Mi, 12 - 2 * n, n < 6 ? 1 : 0);
        dir ^= 1;
    }
    // final result (real plane) in gA_re

    int nq = in_sizes[3];
    gather_kernel<<<(nq + 255) / 256, 256>>>(idx, out, nq);
}